// round 1
// baseline (speedup 1.0000x reference)
#include <cuda_runtime.h>

#define NN 16000
#define D  128
#define NBLK_COLSUM 125   // 16000 / 128 rows per block

// Scratch (device globals; no allocation allowed)
__device__ __align__(16) float g_def[NN * D];       // per-column deficit (8.2 MB)
__device__ float g_part[NBLK_COLSUM * D];           // partial column sums of h

// ---------------------------------------------------------------------------
// K1: zero the deficit array (must precede the scan's atomics; re-run every
// launch since the graph replays).
// ---------------------------------------------------------------------------
__global__ void k_zero() {
    // 16000*128 floats = 512000 float4; grid 1000 x 512 covers exactly.
    unsigned idx = blockIdx.x * blockDim.x + threadIdx.x;
    float4* p = reinterpret_cast<float4*>(g_def);
    p[idx] = make_float4(0.f, 0.f, 0.f, 0.f);
}

// ---------------------------------------------------------------------------
// K2: partial column sums of h (deterministic: no float atomics).
// Block b sums rows [b*128, b*128+128); thread k owns column k.
// ---------------------------------------------------------------------------
__global__ void k_colsum(const float* __restrict__ h) {
    int k = threadIdx.x;
    const float* p = h + (size_t)blockIdx.x * 128 * D + k;
    float s0 = 0.f, s1 = 0.f, s2 = 0.f, s3 = 0.f;
    #pragma unroll 4
    for (int i = 0; i < 128; i += 4) {
        s0 += p[(i + 0) * D];
        s1 += p[(i + 1) * D];
        s2 += p[(i + 2) * D];
        s3 += p[(i + 3) * D];
    }
    g_part[blockIdx.x * D + k] = (s0 + s1) + (s2 + s3);
}

// ---------------------------------------------------------------------------
// K3: stream g (1.024 GB) looking for entries <= 0.  Fast path is a single
// LDG.128 + 3 FMNMX + branch.  Cold path (expected ~30 hits total) subtracts
// h[i] from the deficit of column j via atomics.
// ---------------------------------------------------------------------------
__device__ __forceinline__ void scan_check(float4 v, unsigned t,
                                           const float* __restrict__ h) {
    float m = fminf(fminf(v.x, v.y), fminf(v.z, v.w));
    if (m > 0.0f) return;                      // fast path: all four positive
    unsigned e = t * 4u;                       // element index of v.x
    int i = (int)(e / NN);                     // source row
    int jb = (int)(e % NN);                    // base dst column
    float vv[4] = {v.x, v.y, v.z, v.w};
    const float* hr = h + (size_t)i * D;
    #pragma unroll
    for (int c = 0; c < 4; c++) {
        if (vv[c] <= 0.0f) {
            int j = jb + c;
            for (int k = 0; k < D; k++)
                atomicAdd(&g_def[j * D + k], -hr[k]);
        }
    }
}

__global__ void k_scan(const float4* __restrict__ g4,
                       const float* __restrict__ h) {
    const unsigned total4 = (unsigned)NN * (NN / 4);   // 64,000,000
    unsigned stride = gridDim.x * blockDim.x;
    unsigned t = blockIdx.x * blockDim.x + threadIdx.x;
    // 4x manual unroll: four independent LDG.128 in flight per thread.
    for (; t + 3u * stride < total4; t += 4u * stride) {
        float4 v0 = __ldcs(g4 + t);
        float4 v1 = __ldcs(g4 + t + stride);
        float4 v2 = __ldcs(g4 + t + 2u * stride);
        float4 v3 = __ldcs(g4 + t + 3u * stride);
        scan_check(v0, t, h);
        scan_check(v1, t + stride, h);
        scan_check(v2, t + 2u * stride, h);
        scan_check(v3, t + 3u * stride, h);
    }
    for (; t < total4; t += stride) {
        float4 v = __ldcs(g4 + t);
        scan_check(v, t, h);
    }
}

// ---------------------------------------------------------------------------
// K4: y = h[j] + S + def[j];  out = relu(relu(y@W1+b1)@W2+b2)
// W1,W2 live in 128 KB dynamic smem.  256 threads = two independent halves,
// each half (128 threads, thread = output column k2) processes 8 rows at a
// time so each weight load is amortized over 8 FMAs -> FMA-bound.
// ---------------------------------------------------------------------------
__global__ void __launch_bounds__(256)
k_mlp(const float* __restrict__ h,
      const float* __restrict__ W1, const float* __restrict__ b1,
      const float* __restrict__ W2, const float* __restrict__ b2,
      float* __restrict__ out) {
    extern __shared__ float sm[];
    float* W1s = sm;              // D*D
    float* W2s = sm + D * D;      // D*D
    __shared__ float b1s[D], b2s[D], Ss[D];
    __shared__ __align__(16) float ys[2][8][D];
    __shared__ __align__(16) float ts[2][8][D];

    int tid = threadIdx.x;
    for (int i = tid; i < D * D; i += 256) {
        W1s[i] = W1[i];
        W2s[i] = W2[i];
    }
    if (tid < D) {
        b1s[tid] = b1[tid];
        b2s[tid] = b2[tid];
        float s = 0.f;
        #pragma unroll 5
        for (int b = 0; b < NBLK_COLSUM; b++) s += g_part[b * D + tid];
        Ss[tid] = s;
    }
    __syncthreads();

    int half = tid >> 7;          // 0 or 1
    int k2   = tid & 127;

    const int NGROUPS = NN / 8;   // 2000 groups of 8 rows
    const int gstep = gridDim.x * 2;
    const int iters = (NGROUPS + gstep - 1) / gstep;   // uniform in block

    for (int it = 0; it < iters; it++) {
        int grp = (it * gridDim.x + blockIdx.x) * 2 + half;
        bool active = grp < NGROUPS;
        int row0 = grp * 8;

        if (active) {
            #pragma unroll
            for (int r = 0; r < 8; r++) {
                int j = row0 + r;
                ys[half][r][k2] = h[j * D + k2] + Ss[k2] + g_def[j * D + k2];
            }
        }
        __syncthreads();   // ys ready (also: prior iteration fully drained)

        if (active) {
            float acc[8];
            #pragma unroll
            for (int r = 0; r < 8; r++) acc[r] = b1s[k2];
            #pragma unroll 4
            for (int kc = 0; kc < D; kc += 4) {
                float w0 = W1s[(kc + 0) * D + k2];
                float w1 = W1s[(kc + 1) * D + k2];
                float w2 = W1s[(kc + 2) * D + k2];
                float w3 = W1s[(kc + 3) * D + k2];
                #pragma unroll
                for (int r = 0; r < 8; r++) {
                    float4 y = *reinterpret_cast<const float4*>(&ys[half][r][kc]);
                    acc[r] += y.x * w0 + y.y * w1 + y.z * w2 + y.w * w3;
                }
            }
            #pragma unroll
            for (int r = 0; r < 8; r++) ts[half][r][k2] = fmaxf(acc[r], 0.f);
        }
        __syncthreads();   // ts ready

        if (active) {
            float acc[8];
            #pragma unroll
            for (int r = 0; r < 8; r++) acc[r] = b2s[k2];
            #pragma unroll 4
            for (int kc = 0; kc < D; kc += 4) {
                float w0 = W2s[(kc + 0) * D + k2];
                float w1 = W2s[(kc + 1) * D + k2];
                float w2 = W2s[(kc + 2) * D + k2];
                float w3 = W2s[(kc + 3) * D + k2];
                #pragma unroll
                for (int r = 0; r < 8; r++) {
                    float4 y = *reinterpret_cast<const float4*>(&ts[half][r][kc]);
                    acc[r] += y.x * w0 + y.y * w1 + y.z * w2 + y.w * w3;
                }
            }
            #pragma unroll
            for (int r = 0; r < 8; r++)
                out[(row0 + r) * D + k2] = fmaxf(acc[r], 0.f);
        }
        // next iteration's first __syncthreads protects ys/ts reuse
    }
}

// ---------------------------------------------------------------------------
extern "C" void kernel_launch(void* const* d_in, const int* in_sizes, int n_in,
                              void* d_out, int out_size) {
    const float* g  = (const float*)d_in[0];
    const float* h  = (const float*)d_in[1];
    const float* W1 = (const float*)d_in[2];
    const float* b1 = (const float*)d_in[3];
    const float* W2 = (const float*)d_in[4];
    const float* b2 = (const float*)d_in[5];
    float* out = (float*)d_out;

    cudaFuncSetAttribute(k_mlp, cudaFuncAttributeMaxDynamicSharedMemorySize,
                         2 * D * D * (int)sizeof(float));

    k_zero<<<1000, 512>>>();
    k_colsum<<<NBLK_COLSUM, 128>>>(h);
    k_scan<<<1184, 256>>>((const float4*)g, h);
    k_mlp<<<152, 256, 2 * D * D * sizeof(float)>>>(h, W1, b1, W2, b2, out);
}

// round 2
// speedup vs baseline: 1.1510x; 1.1510x over previous
#include <cuda_runtime.h>

#define NN 16000
#define D  128
#define NBLK_COLSUM 125   // 16000 / 128 rows per block

// Scratch (device globals; no allocation allowed)
__device__ __align__(16) float g_def[NN * D];       // per-column deficit (8.2 MB)
__device__ float g_part[NBLK_COLSUM * D];           // partial column sums of h

// ---------------------------------------------------------------------------
// K1: zero the deficit array (graph replays, so re-zero every launch).
// ---------------------------------------------------------------------------
__global__ void k_zero() {
    unsigned idx = blockIdx.x * blockDim.x + threadIdx.x;
    float4* p = reinterpret_cast<float4*>(g_def);
    p[idx] = make_float4(0.f, 0.f, 0.f, 0.f);
}

// ---------------------------------------------------------------------------
// K2: partial column sums of h (deterministic: no float atomics).
// ---------------------------------------------------------------------------
__global__ void k_colsum(const float* __restrict__ h) {
    int k = threadIdx.x;
    const float* p = h + (size_t)blockIdx.x * 128 * D + k;
    float s0 = 0.f, s1 = 0.f, s2 = 0.f, s3 = 0.f;
    #pragma unroll 4
    for (int i = 0; i < 128; i += 4) {
        s0 += p[(i + 0) * D];
        s1 += p[(i + 1) * D];
        s2 += p[(i + 2) * D];
        s3 += p[(i + 3) * D];
    }
    g_part[blockIdx.x * D + k] = (s0 + s1) + (s2 + s3);
}

// ---------------------------------------------------------------------------
// K3: stream g (1.024 GB) looking for entries <= 0.  Fast path: LDG.128 +
// 3 FMNMX + branch.  Cold path (~30 hits total): atomic deficit update.
// ---------------------------------------------------------------------------
__device__ __forceinline__ void scan_check(float4 v, unsigned t,
                                           const float* __restrict__ h) {
    float m = fminf(fminf(v.x, v.y), fminf(v.z, v.w));
    if (m > 0.0f) return;
    unsigned e = t * 4u;
    int i = (int)(e / NN);
    int jb = (int)(e % NN);
    float vv[4] = {v.x, v.y, v.z, v.w};
    const float* hr = h + (size_t)i * D;
    #pragma unroll
    for (int c = 0; c < 4; c++) {
        if (vv[c] <= 0.0f) {
            int j = jb + c;
            for (int k = 0; k < D; k++)
                atomicAdd(&g_def[j * D + k], -hr[k]);
        }
    }
}

__global__ void k_scan(const float4* __restrict__ g4,
                       const float* __restrict__ h) {
    const unsigned total4 = (unsigned)NN * (NN / 4);   // 64,000,000
    unsigned stride = gridDim.x * blockDim.x;
    unsigned t = blockIdx.x * blockDim.x + threadIdx.x;
    for (; t + 3u * stride < total4; t += 4u * stride) {
        float4 v0 = __ldcs(g4 + t);
        float4 v1 = __ldcs(g4 + t + stride);
        float4 v2 = __ldcs(g4 + t + 2u * stride);
        float4 v3 = __ldcs(g4 + t + 3u * stride);
        scan_check(v0, t, h);
        scan_check(v1, t + stride, h);
        scan_check(v2, t + 2u * stride, h);
        scan_check(v3, t + 3u * stride, h);
    }
    for (; t < total4; t += stride) {
        float4 v = __ldcs(g4 + t);
        scan_check(v, t, h);
    }
}

// ---------------------------------------------------------------------------
// K4 v2: register-blocked GEMM MLP.
// Block = 128 rows x 128 cols.  256 threads as 16x16; each thread owns an
// 8x8 register tile.  Per 4 k-steps: 16 LDS.128 feed 256 FFMAs.
// Layer-1 output (ReLU) overwrites the y tile in smem (barrier-separated).
// ---------------------------------------------------------------------------
__global__ void __launch_bounds__(256)
k_mlp(const float* __restrict__ h,
      const float* __restrict__ W1, const float* __restrict__ b1,
      const float* __restrict__ W2, const float* __restrict__ b2,
      float* __restrict__ out) {
    extern __shared__ float sm[];
    float* W1s = sm;                  // D*D
    float* W2s = sm + D * D;          // D*D
    float* ys  = sm + 2 * D * D;      // D*D  (y tile, then t tile)
    __shared__ float b1s[D], b2s[D], Ss[D];

    int tid = threadIdx.x;
    int tx = tid & 15;                // col group
    int ty = tid >> 4;                // row group
    int c0 = tx * 8;
    int r0 = ty * 8;
    int base_row = blockIdx.x * 128;

    // Load weights + biases + assemble column-sum S.
    for (int i = tid; i < D * D; i += 256) {
        W1s[i] = W1[i];
        W2s[i] = W2[i];
    }
    if (tid < D) {
        b1s[tid] = b1[tid];
        b2s[tid] = b2[tid];
        float s = 0.f;
        #pragma unroll 5
        for (int b = 0; b < NBLK_COLSUM; b++) s += g_part[b * D + tid];
        Ss[tid] = s;
    }
    __syncthreads();

    // Build y tile: y[r][k] = h[row][k] + S[k] + def[row][k]  (float4, coalesced)
    {
        const float4* h4 = reinterpret_cast<const float4*>(h);
        const float4* d4 = reinterpret_cast<const float4*>(g_def);
        const float4* S4 = reinterpret_cast<const float4*>(Ss);
        float4* y4 = reinterpret_cast<float4*>(ys);
        #pragma unroll
        for (int it = 0; it < 16; it++) {
            int idx4 = tid + it * 256;            // 0..4095
            int row = idx4 >> 5;                  // 32 float4 per row
            int c4 = idx4 & 31;
            float4 hv = h4[(size_t)(base_row + row) * 32 + c4];
            float4 dv = d4[(size_t)(base_row + row) * 32 + c4];
            float4 sv = S4[c4];
            y4[idx4] = make_float4(hv.x + dv.x + sv.x, hv.y + dv.y + sv.y,
                                   hv.z + dv.z + sv.z, hv.w + dv.w + sv.w);
        }
    }
    __syncthreads();

    float acc[8][8];

    // ---------------- Layer 1 ----------------
    #pragma unroll
    for (int i = 0; i < 8; i++)
        #pragma unroll
        for (int j = 0; j < 8; j++) acc[i][j] = b1s[c0 + j];

    #pragma unroll 1
    for (int k0 = 0; k0 < D; k0 += 4) {
        float4 a[8], w[8];
        #pragma unroll
        for (int i = 0; i < 8; i++)
            a[i] = *reinterpret_cast<const float4*>(&ys[(r0 + i) * D + k0]);
        #pragma unroll
        for (int kk = 0; kk < 4; kk++) {
            w[kk * 2]     = *reinterpret_cast<const float4*>(&W1s[(k0 + kk) * D + c0]);
            w[kk * 2 + 1] = *reinterpret_cast<const float4*>(&W1s[(k0 + kk) * D + c0 + 4]);
        }
        #pragma unroll
        for (int kk = 0; kk < 4; kk++) {
            float4 w0 = w[kk * 2], w1 = w[kk * 2 + 1];
            #pragma unroll
            for (int i = 0; i < 8; i++) {
                float av = reinterpret_cast<const float*>(&a[i])[kk];
                acc[i][0] += av * w0.x; acc[i][1] += av * w0.y;
                acc[i][2] += av * w0.z; acc[i][3] += av * w0.w;
                acc[i][4] += av * w1.x; acc[i][5] += av * w1.y;
                acc[i][6] += av * w1.z; acc[i][7] += av * w1.w;
            }
        }
    }
    __syncthreads();   // all layer-1 reads of ys done

    // Write t = relu(layer1) back into ys
    #pragma unroll
    for (int i = 0; i < 8; i++) {
        float4 lo = make_float4(fmaxf(acc[i][0], 0.f), fmaxf(acc[i][1], 0.f),
                                fmaxf(acc[i][2], 0.f), fmaxf(acc[i][3], 0.f));
        float4 hi = make_float4(fmaxf(acc[i][4], 0.f), fmaxf(acc[i][5], 0.f),
                                fmaxf(acc[i][6], 0.f), fmaxf(acc[i][7], 0.f));
        *reinterpret_cast<float4*>(&ys[(r0 + i) * D + c0])     = lo;
        *reinterpret_cast<float4*>(&ys[(r0 + i) * D + c0 + 4]) = hi;
    }
    __syncthreads();   // t tile ready

    // ---------------- Layer 2 ----------------
    #pragma unroll
    for (int i = 0; i < 8; i++)
        #pragma unroll
        for (int j = 0; j < 8; j++) acc[i][j] = b2s[c0 + j];

    #pragma unroll 1
    for (int k0 = 0; k0 < D; k0 += 4) {
        float4 a[8], w[8];
        #pragma unroll
        for (int i = 0; i < 8; i++)
            a[i] = *reinterpret_cast<const float4*>(&ys[(r0 + i) * D + k0]);
        #pragma unroll
        for (int kk = 0; kk < 4; kk++) {
            w[kk * 2]     = *reinterpret_cast<const float4*>(&W2s[(k0 + kk) * D + c0]);
            w[kk * 2 + 1] = *reinterpret_cast<const float4*>(&W2s[(k0 + kk) * D + c0 + 4]);
        }
        #pragma unroll
        for (int kk = 0; kk < 4; kk++) {
            float4 w0 = w[kk * 2], w1 = w[kk * 2 + 1];
            #pragma unroll
            for (int i = 0; i < 8; i++) {
                float av = reinterpret_cast<const float*>(&a[i])[kk];
                acc[i][0] += av * w0.x; acc[i][1] += av * w0.y;
                acc[i][2] += av * w0.z; acc[i][3] += av * w0.w;
                acc[i][4] += av * w1.x; acc[i][5] += av * w1.y;
                acc[i][6] += av * w1.z; acc[i][7] += av * w1.w;
            }
        }
    }

    // Output with outer ReLU (coalesced STG.128)
    #pragma unroll
    for (int i = 0; i < 8; i++) {
        float4 lo = make_float4(fmaxf(acc[i][0], 0.f), fmaxf(acc[i][1], 0.f),
                                fmaxf(acc[i][2], 0.f), fmaxf(acc[i][3], 0.f));
        float4 hi = make_float4(fmaxf(acc[i][4], 0.f), fmaxf(acc[i][5], 0.f),
                                fmaxf(acc[i][6], 0.f), fmaxf(acc[i][7], 0.f));
        size_t o = (size_t)(base_row + r0 + i) * D + c0;
        *reinterpret_cast<float4*>(&out[o])     = lo;
        *reinterpret_cast<float4*>(&out[o + 4]) = hi;
    }
}

// ---------------------------------------------------------------------------
extern "C" void kernel_launch(void* const* d_in, const int* in_sizes, int n_in,
                              void* d_out, int out_size) {
    const float* g  = (const float*)d_in[0];
    const float* h  = (const float*)d_in[1];
    const float* W1 = (const float*)d_in[2];
    const float* b1 = (const float*)d_in[3];
    const float* W2 = (const float*)d_in[4];
    const float* b2 = (const float*)d_in[5];
    float* out = (float*)d_out;

    const int SMEM = 3 * D * D * (int)sizeof(float);   // 192 KB
    cudaFuncSetAttribute(k_mlp, cudaFuncAttributeMaxDynamicSharedMemorySize, SMEM);

    k_zero<<<1000, 512>>>();
    k_colsum<<<NBLK_COLSUM, 128>>>(h);
    k_scan<<<1184, 256>>>((const float4*)g, h);
    k_mlp<<<125, 256, SMEM>>>(h, W1, b1, W2, b2, out);
}